// round 14
// baseline (speedup 1.0000x reference)
#include <cuda_runtime.h>
#include <cuda_fp16.h>
#include <cstdint>

#define HN   128
#define MAXN 100000
#define MAXE 1600000
#define MAXS 10000
#define TM   64
#define WS   136            // padded fp16 plane stride (ldsm conflict-free)
#define PLANE (HN * WS)     // 17408
#define TMWS  (TM * WS)     // 8704

// ---------------- scratch (static device globals; no allocation) ----------------
__device__ __align__(16) __half g_hA[(size_t)MAXN * HN];
__device__ __align__(16) __half g_hB[(size_t)MAXN * HN];
__device__ float g_agg0[MAXN];
__device__ int   g_ei[2 * MAXE];
__device__ int   g_comp[MAXN];
__device__ int   g_deg[MAXN];
__device__ int   g_offs[MAXN + 1];
__device__ int   g_cursor[MAXN];
__device__ int   g_csr[MAXE];
__device__ int   g_is64;
__device__ __align__(16) __half g_whalf[5 * PLANE];   // 5 matrices, one fp16 plane each

// ---------------- helpers ----------------
__device__ __forceinline__ uint32_t sptr(const void* p) {
    return (uint32_t)__cvta_generic_to_shared(p);
}
__device__ __forceinline__ void ldsm4(uint32_t a, uint32_t& r0, uint32_t& r1,
                                      uint32_t& r2, uint32_t& r3) {
    asm volatile("ldmatrix.sync.aligned.m8n8.x4.shared.b16 {%0,%1,%2,%3},[%4];"
                 : "=r"(r0), "=r"(r1), "=r"(r2), "=r"(r3) : "r"(a));
}
__device__ __forceinline__ void ldsm4t(uint32_t a, uint32_t& r0, uint32_t& r1,
                                       uint32_t& r2, uint32_t& r3) {
    asm volatile("ldmatrix.sync.aligned.m8n8.x4.trans.shared.b16 {%0,%1,%2,%3},[%4];"
                 : "=r"(r0), "=r"(r1), "=r"(r2), "=r"(r3) : "r"(a));
}
__device__ __forceinline__ void mma16816(float* c, uint32_t a0, uint32_t a1, uint32_t a2,
                                         uint32_t a3, uint32_t b0, uint32_t b1) {
    asm volatile(
        "mma.sync.aligned.m16n8k16.row.col.f32.f16.f16.f32 "
        "{%0,%1,%2,%3},{%4,%5,%6,%7},{%8,%9},{%0,%1,%2,%3};"
        : "+f"(c[0]), "+f"(c[1]), "+f"(c[2]), "+f"(c[3])
        : "r"(a0), "r"(a1), "r"(a2), "r"(a3), "r"(b0), "r"(b1));
}
__device__ __forceinline__ void addh2(float4& a, uint2 v) {
    float2 f0 = __half22float2(*(__half2*)&v.x);
    float2 f1 = __half22float2(*(__half2*)&v.y);
    a.x += f0.x; a.y += f0.y; a.z += f1.x; a.w += f1.y;
}

// ---------------- init: parallel dtype detect ----------------
__global__ void k_init(const unsigned long long* __restrict__ p) {
    int lane = threadIdx.x;
    unsigned long long v = (lane < 64) ? p[lane] : 0ull;
    unsigned any_hi = __ballot_sync(0xffffffffu, (lane < 64) && (v >> 32));
    __shared__ int hi;
    if (threadIdx.x == 0) hi = 0;
    __syncthreads();
    if (any_hi && (lane & 31) == 0) atomicOr(&hi, 1);
    __syncthreads();
    if (threadIdx.x == 0) g_is64 = hi ? 0 : 1;
}

// convert both halves of edge_index; histogram degrees from the dst half
__global__ void k_convert_ei(const void* __restrict__ in, int* __restrict__ out,
                             int* __restrict__ deg, int E) {
    int i = blockIdx.x * blockDim.x + threadIdx.x;
    if (i >= 2 * E) return;
    int v;
    if (g_is64) v = (int)(((const long long*)in)[i]);
    else        v = ((const int*)in)[i];
    out[i] = v;
    if (i >= E) atomicAdd(deg + v, 1);
}
__global__ void k_comp2(const void* __restrict__ n2s, const void* __restrict__ s2g,
                        int* __restrict__ comp, int n) {
    int i = blockIdx.x * blockDim.x + threadIdx.x;
    if (i >= n) return;
    int s, g;
    if (g_is64) {
        s = (int)(((const long long*)n2s)[i]);
        g = (int)(((const long long*)s2g)[s]);
    } else {
        s = ((const int*)n2s)[i];
        g = ((const int*)s2g)[s];
    }
    comp[i] = g;
}

// ---------------- utility ----------------
__global__ void k_zero4(float* __restrict__ p, int n4) {
    int i = blockIdx.x * blockDim.x + threadIdx.x;
    if (i < n4) ((float4*)p)[i] = make_float4(0.f, 0.f, 0.f, 0.f);
}
__global__ void k_zero2i(int* __restrict__ a, int* __restrict__ b, int n) {
    int i = blockIdx.x * blockDim.x + threadIdx.x;
    if (i < n) { a[i] = 0; b[i] = 0; }
}

// ---------------- W convert: all 5 matrices -> fp16 planes (one launch) ----------------
__global__ void k_cvtW5(const float* __restrict__ c1W2, const float* __restrict__ cW1,
                        const float* __restrict__ cW2, __half* __restrict__ wh) {
    int i = blockIdx.x * blockDim.x + threadIdx.x;
    if (i >= 5 * HN * HN) return;
    int m = i / (HN * HN), r = i % (HN * HN);
    const float* src = (m == 0) ? c1W2 : (m == 1) ? cW1 : (m == 2) ? cW2
                     : (m == 3) ? (cW1 + HN * HN) : (cW2 + HN * HN);
    int k = r >> 7, n = r & 127;
    wh[(size_t)m * PLANE + k * WS + n] = __float2half_rn(src[r]);
}

// ---------------- CSR build ----------------
__global__ void k_scan(const int* __restrict__ deg, int* __restrict__ offs, int n) {
    __shared__ int sums[1024];
    int tid = threadIdx.x;
    int chunk = (n + 1023) / 1024;
    int start = tid * chunk;
    int end   = start + chunk; if (end > n) end = n;
    int s = 0;
    for (int i = start; i < end; i++) s += deg[i];
    sums[tid] = s;
    __syncthreads();
    for (int off = 1; off < 1024; off <<= 1) {
        int v = 0;
        if (tid >= off) v = sums[tid - off];
        __syncthreads();
        if (tid >= off) sums[tid] += v;
        __syncthreads();
    }
    int run = (tid == 0) ? 0 : sums[tid - 1];
    for (int i = start; i < end; i++) { offs[i] = run; run += deg[i]; }
    if (end == n) offs[n] = run;
}
__global__ void k_scatter(const int* __restrict__ src, const int* __restrict__ dst,
                          const int* __restrict__ offs, int* __restrict__ cursor,
                          int* __restrict__ csr, int E) {
    int e = blockIdx.x * blockDim.x + threadIdx.x;
    if (e >= E) return;
    int d = dst[e];
    int p = atomicAdd(cursor + d, 1);
    csr[offs[d] + p] = src[e];
}

// ---------------- layer-1 scalar aggregation ----------------
__global__ void k_agg0(const int* __restrict__ offs, const int* __restrict__ csr,
                       const float* __restrict__ x, float* __restrict__ agg, int N) {
    int warp = (blockIdx.x * blockDim.x + threadIdx.x) >> 5;
    int lane = threadIdx.x & 31;
    if (warp >= N) return;
    int s = offs[warp], e = offs[warp + 1];
    float acc = 0.f;
    for (int i = s + lane; i < e; i += 32) acc += __ldg(x + csr[i]);
#pragma unroll
    for (int o = 16; o; o >>= 1) acc += __shfl_xor_sync(0xffffffffu, acc, o);
    if (lane == 0) agg[warp] = acc + x[warp];
}

// ---------------- MMA: acc[8][4] = A[64,128]f16 @ W[128,128]f16 (warp m16 x n64) ----------------
__device__ __forceinline__ void mma_phase(
    const __half* A, const __half* B,
    int mrow0, int nbase, int lane, float acc[8][4]) {
#pragma unroll
    for (int j = 0; j < 8; j++)
#pragma unroll
        for (int c = 0; c < 4; c++) acc[j][c] = 0.f;

    int aoff = (mrow0 + (lane & 15)) * WS + ((lane >> 4) << 3);
    int brow = (lane & 15) * WS;
    int bn   = (lane >> 4) << 3;

#pragma unroll
    for (int kt = 0; kt < 8; kt++) {
        uint32_t a0, a1, a2, a3;
        ldsm4(sptr(A + aoff + kt * 16), a0, a1, a2, a3);
#pragma unroll
        for (int jj = 0; jj < 4; jj++) {
            int nj = nbase + jj * 16;
            uint32_t b0, b1, b2, b3;
            ldsm4t(sptr(B + kt * 16 * WS + brow + nj + bn), b0, b1, b2, b3);
            mma16816(acc[2 * jj],     a0, a1, a2, a3, b0, b1);
            mma16816(acc[2 * jj + 1], a0, a1, a2, a3, b2, b3);
        }
    }
}

// ---------------- fused GIN layer (persistent, fp16, fused CSR gather + optional pool) ----------------
// smem: W1 (PLANE) + W2 (PLANE) + A (TMWS) + T (TMWS) = 52224 elems = 104448 B -> 2 blocks/SM
#define OFF_A (2 * PLANE)
#define OFF_T (2 * PLANE + TMWS)
#define SMEM_ELEMS (2 * PLANE + 2 * TMWS)

extern __shared__ __half sb[];

__global__ __launch_bounds__(256) void k_layer(
    const __half* __restrict__ Hprev,                     // gathered input (modes 1/2)
    const int* __restrict__ offs, const int* __restrict__ csr,
    const float* __restrict__ vscal, const float* __restrict__ W1v,
    const __half* __restrict__ W1, const float* __restrict__ b1,
    const __half* __restrict__ W2, const float* __restrict__ b2,
    __half* __restrict__ Out,
    const int* __restrict__ comp, float* __restrict__ outPool,
    int nrows, int mode) {

    __shared__ float sv[TM];
    __shared__ float spool[HN];
    int tid  = threadIdx.x;
    int lane = tid & 31;
    int w    = tid >> 5;
    int mrow0 = (w >> 1) * 16;
    int nbase = (w & 1) * 64;

    __half* sW1 = sb;
    __half* sW2 = sb + PLANE;
    __half* sA  = sb + OFF_A;
    __half* sT  = sb + OFF_T;

    const int U4 = PLANE * 2 / 16;
    for (int i = tid; i < U4; i += 256) {
        ((uint4*)sW2)[i] = ((const uint4*)W2)[i];
        if (mode != 0) ((uint4*)sW1)[i] = ((const uint4*)W1)[i];
    }

    int ntiles = (nrows + TM - 1) / TM;
    for (int t = blockIdx.x; t < ntiles; t += gridDim.x) {
        int row0 = t * TM;
        int tr = nrows - row0; if (tr > TM) tr = TM;
        __syncthreads();

        if (mode == 0) {
            if (tid < TM) sv[tid] = (tid < tr) ? vscal[row0 + tid] : 0.f;
            __syncthreads();
            for (int i = tid; i < TM * HN; i += 256) {
                int r = i >> 7, c = i & 127;
                float v = fmaxf(fmaf(sv[r], __ldg(W1v + c), __ldg(b1 + c)), 0.f);
                sT[r * WS + c] = __float2half_rn(v);
            }
            __syncthreads();
        } else {
            if (mode == 2 && tid < HN) spool[tid] = 0.f;
            // fused A-phase: gather + self-sum straight into sA (fp32 accumulate)
            // warp w handles rows w*8 .. w*8+7; lane covers 4 cols (uint2 = 8B)
#pragma unroll 1
            for (int lr = w * 8; lr < w * 8 + 8; lr++) {
                int gr = row0 + lr;
                float4 acc4 = make_float4(0.f, 0.f, 0.f, 0.f);
                if (gr < nrows) {
                    addh2(acc4, __ldg(((const uint2*)(Hprev + (size_t)gr * HN)) + lane)); // self
                    int s = __ldg(offs + gr), e = __ldg(offs + gr + 1);
                    int i = s;
#pragma unroll 1
                    for (; i + 8 <= e; i += 8) {
                        int idx[8];
#pragma unroll
                        for (int u = 0; u < 8; u++) idx[u] = __ldg(csr + i + u);
                        uint2 v[8];
#pragma unroll
                        for (int u = 0; u < 8; u++)
                            v[u] = __ldg(((const uint2*)(Hprev + (size_t)idx[u] * HN)) + lane);
#pragma unroll
                        for (int u = 0; u < 8; u++) addh2(acc4, v[u]);
                    }
                    for (; i < e; i++)
                        addh2(acc4, __ldg(((const uint2*)(Hprev + (size_t)__ldg(csr + i) * HN)) + lane));
                }
                uint2 o;
                __half2 p0 = __floats2half2_rn(acc4.x, acc4.y);
                __half2 p1 = __floats2half2_rn(acc4.z, acc4.w);
                o.x = *(uint32_t*)&p0; o.y = *(uint32_t*)&p1;
                *(uint2*)(sA + lr * WS + lane * 4) = o;
            }
            __syncthreads();

            float acc[8][4];
            mma_phase(sA, sW1, mrow0, nbase, lane, acc);

            int r0 = mrow0 + (lane >> 2);
#pragma unroll
            for (int j = 0; j < 8; j++) {
                int c = nbase + 8 * j + (lane & 3) * 2;
                float bx = __ldg(b1 + c), by = __ldg(b1 + c + 1);
                *(__half2*)(sT + r0 * WS + c) =
                    __floats2half2_rn(fmaxf(acc[j][0] + bx, 0.f), fmaxf(acc[j][1] + by, 0.f));
                *(__half2*)(sT + (r0 + 8) * WS + c) =
                    __floats2half2_rn(fmaxf(acc[j][2] + bx, 0.f), fmaxf(acc[j][3] + by, 0.f));
            }
            __syncthreads();
        }

        // phase 2: relu(T @ W2 + b2)
        float acc[8][4];
        mma_phase(sT, sW2, mrow0, nbase, lane, acc);

        int r0 = mrow0 + (lane >> 2);
        if (mode == 2) {
            int gfirst = __ldg(comp + row0);
            int glast  = __ldg(comp + row0 + tr - 1);
            if (gfirst == glast) {
                // fast path: whole tile pools into one graph; warp shfl column-reduce
#pragma unroll
                for (int j = 0; j < 8; j++) {
                    int c = nbase + 8 * j + (lane & 3) * 2;
                    float bx = __ldg(b2 + c), by = __ldg(b2 + c + 1);
                    float v0 = 0.f, v1 = 0.f;
                    if (r0 < tr)     { v0 += fmaxf(acc[j][0] + bx, 0.f); v1 += fmaxf(acc[j][1] + by, 0.f); }
                    if (r0 + 8 < tr) { v0 += fmaxf(acc[j][2] + bx, 0.f); v1 += fmaxf(acc[j][3] + by, 0.f); }
#pragma unroll
                    for (int o = 4; o <= 16; o <<= 1) {
                        v0 += __shfl_xor_sync(0xffffffffu, v0, o);
                        v1 += __shfl_xor_sync(0xffffffffu, v1, o);
                    }
                    if (lane < 4) {
                        atomicAdd(&spool[c], v0);
                        atomicAdd(&spool[c + 1], v1);
                    }
                }
                __syncthreads();
                if (tid < HN) atomicAdd(outPool + (size_t)gfirst * HN + tid, spool[tid]);
            } else {
                // boundary tile (rare): per-element global atomics
#pragma unroll
                for (int j = 0; j < 8; j++) {
                    int c = nbase + 8 * j + (lane & 3) * 2;
                    float bx = __ldg(b2 + c), by = __ldg(b2 + c + 1);
                    if (r0 < tr) {
                        int g = __ldg(comp + row0 + r0);
                        atomicAdd(outPool + (size_t)g * HN + c,     fmaxf(acc[j][0] + bx, 0.f));
                        atomicAdd(outPool + (size_t)g * HN + c + 1, fmaxf(acc[j][1] + by, 0.f));
                    }
                    if (r0 + 8 < tr) {
                        int g = __ldg(comp + row0 + r0 + 8);
                        atomicAdd(outPool + (size_t)g * HN + c,     fmaxf(acc[j][2] + bx, 0.f));
                        atomicAdd(outPool + (size_t)g * HN + c + 1, fmaxf(acc[j][3] + by, 0.f));
                    }
                }
            }
        } else {
#pragma unroll
            for (int j = 0; j < 8; j++) {
                int c = nbase + 8 * j + (lane & 3) * 2;
                float bx = __ldg(b2 + c), by = __ldg(b2 + c + 1);
                int gr0 = row0 + r0, gr1 = gr0 + 8;
                if (gr0 < nrows)
                    *(__half2*)(Out + (size_t)gr0 * HN + c) =
                        __floats2half2_rn(fmaxf(acc[j][0] + bx, 0.f), fmaxf(acc[j][1] + by, 0.f));
                if (gr1 < nrows)
                    *(__half2*)(Out + (size_t)gr1 * HN + c) =
                        __floats2half2_rn(fmaxf(acc[j][2] + bx, 0.f), fmaxf(acc[j][3] + by, 0.f));
            }
        }
    }
}

// ---------------- launch ----------------
extern "C" void kernel_launch(void* const* d_in, const int* in_sizes, int n_in,
                              void* d_out, int out_size) {
    const float* x     = (const float*)d_in[0];
    const void*  ei    = d_in[1];
    const void*  n2s   = d_in[2];
    const void*  s2g_i = d_in[3];
    const float* c1W1  = (const float*)d_in[4];
    const float* c1b1  = (const float*)d_in[5];
    const float* c1W2  = (const float*)d_in[6];
    const float* c1b2  = (const float*)d_in[7];
    const float* cW1   = (const float*)d_in[8];
    const float* cb1   = (const float*)d_in[9];
    const float* cW2   = (const float*)d_in[10];
    const float* cb2   = (const float*)d_in[11];

    int N = in_sizes[0];
    int E = in_sizes[1] / 2;
    int G = out_size / HN;

    __half *hA, *hB, *wh;
    float *agg0;
    int *eiX, *comp, *deg, *offs, *cursor, *csr;
    cudaGetSymbolAddress((void**)&hA,     g_hA);
    cudaGetSymbolAddress((void**)&hB,     g_hB);
    cudaGetSymbolAddress((void**)&agg0,   g_agg0);
    cudaGetSymbolAddress((void**)&eiX,    g_ei);
    cudaGetSymbolAddress((void**)&comp,   g_comp);
    cudaGetSymbolAddress((void**)&deg,    g_deg);
    cudaGetSymbolAddress((void**)&offs,   g_offs);
    cudaGetSymbolAddress((void**)&cursor, g_cursor);
    cudaGetSymbolAddress((void**)&csr,    g_csr);
    cudaGetSymbolAddress((void**)&wh,     g_whalf);

    const int SMEM = SMEM_ELEMS * 2;   // 104448 B -> 2 blocks/SM
    cudaFuncSetAttribute(k_layer, cudaFuncAttributeMaxDynamicSharedMemorySize, SMEM);

    // init (parallel detect), zero deg/cursor, normalize indices
    k_init<<<1, 64>>>((const unsigned long long*)ei);
    k_zero2i<<<(N + 255) / 256, 256>>>(deg, cursor, N);
    k_convert_ei<<<(2 * E + 255) / 256, 256>>>(ei, eiX, deg, E);
    k_comp2<<<(N + 255) / 256, 256>>>(n2s, s2g_i, comp, N);

    // all 5 weight matrices -> fp16 planes (one launch)
    k_cvtW5<<<(5 * HN * HN + 255) / 256, 256>>>(c1W2, cW1, cW2, wh);

    // CSR build (dst-major)
    k_scan<<<1, 1024>>>(deg, offs, N);
    k_scatter<<<(E + 255) / 256, 256>>>(eiX, eiX + E, offs, cursor, csr, E);

    int ablocks = (N * 32 + 255) / 256;
    const int LGRID = 296;   // 2 blocks/SM

    // layer 1: scalar agg + fused expansion/MMA -> hB
    k_agg0<<<ablocks, 256>>>(offs, csr, x, agg0, N);
    k_layer<<<LGRID, 256, SMEM>>>(nullptr, nullptr, nullptr, agg0, c1W1,
                                  nullptr, c1b1, wh + 0 * PLANE, c1b2,
                                  hB, nullptr, nullptr, N, 0);

    // layer 2: fused gather(hB) + dual MMA -> hA
    k_layer<<<LGRID, 256, SMEM>>>(hB, offs, csr, nullptr, nullptr,
                                  wh + 1 * PLANE, cb1, wh + 2 * PLANE, cb2,
                                  hA, nullptr, nullptr, N, 1);

    // layer 3: fused gather(hA) + dual MMA + fused pooling -> d_out
    k_zero4<<<((G * HN / 4) + 255) / 256, 256>>>((float*)d_out, G * HN / 4);
    k_layer<<<LGRID, 256, SMEM>>>(hA, offs, csr, nullptr, nullptr,
                                  wh + 3 * PLANE, cb1 + HN, wh + 4 * PLANE, cb2 + HN,
                                  nullptr, comp, (float*)d_out, N, 2);
}

// round 15
// speedup vs baseline: 1.2509x; 1.2509x over previous
#include <cuda_runtime.h>
#include <cuda_fp16.h>
#include <cstdint>

#define HN   128
#define MAXN 100000
#define MAXE 1600000
#define MAXS 10000
#define TM   64
#define WS   136            // padded fp16 plane stride (ldsm conflict-free)
#define PLANE (HN * WS)     // 17408
#define TMWS  (TM * WS)     // 8704

// ---------------- scratch (static device globals; no allocation) ----------------
__device__ __align__(16) __half g_hA[(size_t)MAXN * HN];
__device__ __align__(16) __half g_hB[(size_t)MAXN * HN];
__device__ float g_agg0[MAXN];
__device__ int   g_ei[2 * MAXE];
__device__ int   g_comp[MAXN];
__device__ int   g_deg[MAXN];
__device__ int   g_offs[MAXN + 1];
__device__ int   g_cursor[MAXN];
__device__ int   g_csr[MAXE];
__device__ int   g_is64;
__device__ __align__(16) __half g_whalf[5 * PLANE];   // 5 matrices, one fp16 plane each

// ---------------- helpers ----------------
__device__ __forceinline__ uint32_t sptr(const void* p) {
    return (uint32_t)__cvta_generic_to_shared(p);
}
__device__ __forceinline__ void ldsm4(uint32_t a, uint32_t& r0, uint32_t& r1,
                                      uint32_t& r2, uint32_t& r3) {
    asm volatile("ldmatrix.sync.aligned.m8n8.x4.shared.b16 {%0,%1,%2,%3},[%4];"
                 : "=r"(r0), "=r"(r1), "=r"(r2), "=r"(r3) : "r"(a));
}
__device__ __forceinline__ void ldsm4t(uint32_t a, uint32_t& r0, uint32_t& r1,
                                       uint32_t& r2, uint32_t& r3) {
    asm volatile("ldmatrix.sync.aligned.m8n8.x4.trans.shared.b16 {%0,%1,%2,%3},[%4];"
                 : "=r"(r0), "=r"(r1), "=r"(r2), "=r"(r3) : "r"(a));
}
__device__ __forceinline__ void mma16816(float* c, uint32_t a0, uint32_t a1, uint32_t a2,
                                         uint32_t a3, uint32_t b0, uint32_t b1) {
    asm volatile(
        "mma.sync.aligned.m16n8k16.row.col.f32.f16.f16.f32 "
        "{%0,%1,%2,%3},{%4,%5,%6,%7},{%8,%9},{%0,%1,%2,%3};"
        : "+f"(c[0]), "+f"(c[1]), "+f"(c[2]), "+f"(c[3])
        : "r"(a0), "r"(a1), "r"(a2), "r"(a3), "r"(b0), "r"(b1));
}
// accumulate 8 fp16 (uint4) into 8 fp32
__device__ __forceinline__ void addh4(float* a, uint4 v) {
    float2 f0 = __half22float2(*(__half2*)&v.x);
    float2 f1 = __half22float2(*(__half2*)&v.y);
    float2 f2 = __half22float2(*(__half2*)&v.z);
    float2 f3 = __half22float2(*(__half2*)&v.w);
    a[0] += f0.x; a[1] += f0.y; a[2] += f1.x; a[3] += f1.y;
    a[4] += f2.x; a[5] += f2.y; a[6] += f3.x; a[7] += f3.y;
}

// ---------------- init: parallel dtype detect ----------------
__global__ void k_init(const unsigned long long* __restrict__ p) {
    int lane = threadIdx.x;
    unsigned long long v = (lane < 64) ? p[lane] : 0ull;
    unsigned any_hi = __ballot_sync(0xffffffffu, (lane < 64) && (v >> 32));
    __shared__ int hi;
    if (threadIdx.x == 0) hi = 0;
    __syncthreads();
    if (any_hi && (lane & 31) == 0) atomicOr(&hi, 1);
    __syncthreads();
    if (threadIdx.x == 0) g_is64 = hi ? 0 : 1;
}

// convert both halves of edge_index; histogram degrees from the dst half
__global__ void k_convert_ei(const void* __restrict__ in, int* __restrict__ out,
                             int* __restrict__ deg, int E) {
    int i = blockIdx.x * blockDim.x + threadIdx.x;
    if (i >= 2 * E) return;
    int v;
    if (g_is64) v = (int)(((const long long*)in)[i]);
    else        v = ((const int*)in)[i];
    out[i] = v;
    if (i >= E) atomicAdd(deg + v, 1);
}
__global__ void k_comp2(const void* __restrict__ n2s, const void* __restrict__ s2g,
                        int* __restrict__ comp, int n) {
    int i = blockIdx.x * blockDim.x + threadIdx.x;
    if (i >= n) return;
    int s, g;
    if (g_is64) {
        s = (int)(((const long long*)n2s)[i]);
        g = (int)(((const long long*)s2g)[s]);
    } else {
        s = ((const int*)n2s)[i];
        g = ((const int*)s2g)[s];
    }
    comp[i] = g;
}

// ---------------- utility ----------------
__global__ void k_zero4(float* __restrict__ p, int n4) {
    int i = blockIdx.x * blockDim.x + threadIdx.x;
    if (i < n4) ((float4*)p)[i] = make_float4(0.f, 0.f, 0.f, 0.f);
}
__global__ void k_zero2i(int* __restrict__ a, int* __restrict__ b, int n) {
    int i = blockIdx.x * blockDim.x + threadIdx.x;
    if (i < n) { a[i] = 0; b[i] = 0; }
}

// ---------------- W convert: all 5 matrices -> fp16 planes (one launch) ----------------
__global__ void k_cvtW5(const float* __restrict__ c1W2, const float* __restrict__ cW1,
                        const float* __restrict__ cW2, __half* __restrict__ wh) {
    int i = blockIdx.x * blockDim.x + threadIdx.x;
    if (i >= 5 * HN * HN) return;
    int m = i / (HN * HN), r = i % (HN * HN);
    const float* src = (m == 0) ? c1W2 : (m == 1) ? cW1 : (m == 2) ? cW2
                     : (m == 3) ? (cW1 + HN * HN) : (cW2 + HN * HN);
    int k = r >> 7, n = r & 127;
    wh[(size_t)m * PLANE + k * WS + n] = __float2half_rn(src[r]);
}

// ---------------- CSR build ----------------
__global__ void k_scan(const int* __restrict__ deg, int* __restrict__ offs, int n) {
    __shared__ int sums[1024];
    int tid = threadIdx.x;
    int chunk = (n + 1023) / 1024;
    int start = tid * chunk;
    int end   = start + chunk; if (end > n) end = n;
    int s = 0;
    for (int i = start; i < end; i++) s += deg[i];
    sums[tid] = s;
    __syncthreads();
    for (int off = 1; off < 1024; off <<= 1) {
        int v = 0;
        if (tid >= off) v = sums[tid - off];
        __syncthreads();
        if (tid >= off) sums[tid] += v;
        __syncthreads();
    }
    int run = (tid == 0) ? 0 : sums[tid - 1];
    for (int i = start; i < end; i++) { offs[i] = run; run += deg[i]; }
    if (end == n) offs[n] = run;
}
__global__ void k_scatter(const int* __restrict__ src, const int* __restrict__ dst,
                          const int* __restrict__ offs, int* __restrict__ cursor,
                          int* __restrict__ csr, int E) {
    int e = blockIdx.x * blockDim.x + threadIdx.x;
    if (e >= E) return;
    int d = dst[e];
    int p = atomicAdd(cursor + d, 1);
    csr[offs[d] + p] = src[e];
}

// ---------------- layer-1 scalar aggregation ----------------
__global__ void k_agg0(const int* __restrict__ offs, const int* __restrict__ csr,
                       const float* __restrict__ x, float* __restrict__ agg, int N) {
    int warp = (blockIdx.x * blockDim.x + threadIdx.x) >> 5;
    int lane = threadIdx.x & 31;
    if (warp >= N) return;
    int s = offs[warp], e = offs[warp + 1];
    float acc = 0.f;
    for (int i = s + lane; i < e; i += 32) acc += __ldg(x + csr[i]);
#pragma unroll
    for (int o = 16; o; o >>= 1) acc += __shfl_xor_sync(0xffffffffu, acc, o);
    if (lane == 0) agg[warp] = acc + x[warp];
}

// ---------------- fp16 vector aggregation incl. self (half-warp per node, uint4) ----------------
__global__ __launch_bounds__(256) void k_agg_csr(
    const int* __restrict__ offs, const int* __restrict__ csr,
    const __half* __restrict__ h, __half* __restrict__ out, int N) {
    int hw = (blockIdx.x * blockDim.x + threadIdx.x) >> 4;   // half-warp = node
    int ln = threadIdx.x & 15;                               // 16 lanes x 16B = 256B row
    if (hw >= N) return;
    int s = __ldg(offs + hw), e = __ldg(offs + hw + 1);
    float acc[8] = {0.f, 0.f, 0.f, 0.f, 0.f, 0.f, 0.f, 0.f};
    addh4(acc, __ldg(((const uint4*)(h + (size_t)hw * HN)) + ln));   // self
    int i = s;
#pragma unroll 1
    for (; i + 8 <= e; i += 8) {
        int idx[8];
#pragma unroll
        for (int u = 0; u < 8; u++) idx[u] = __ldg(csr + i + u);
        uint4 v[8];
#pragma unroll
        for (int u = 0; u < 8; u++)
            v[u] = __ldg(((const uint4*)(h + (size_t)idx[u] * HN)) + ln);
#pragma unroll
        for (int u = 0; u < 8; u++) addh4(acc, v[u]);
    }
    for (; i < e; i++)
        addh4(acc, __ldg(((const uint4*)(h + (size_t)__ldg(csr + i) * HN)) + ln));
    uint4 o;
    __half2 p0 = __floats2half2_rn(acc[0], acc[1]);
    __half2 p1 = __floats2half2_rn(acc[2], acc[3]);
    __half2 p2 = __floats2half2_rn(acc[4], acc[5]);
    __half2 p3 = __floats2half2_rn(acc[6], acc[7]);
    o.x = *(uint32_t*)&p0; o.y = *(uint32_t*)&p1;
    o.z = *(uint32_t*)&p2; o.w = *(uint32_t*)&p3;
    ((uint4*)(out + (size_t)hw * HN))[ln] = o;
}

// ---------------- MMA: acc[8][4] = A[64,128]f16 @ W[128,128]f16 (warp m16 x n64) ----------------
__device__ __forceinline__ void mma_phase(
    const __half* A, const __half* B,
    int mrow0, int nbase, int lane, float acc[8][4]) {
#pragma unroll
    for (int j = 0; j < 8; j++)
#pragma unroll
        for (int c = 0; c < 4; c++) acc[j][c] = 0.f;

    int aoff = (mrow0 + (lane & 15)) * WS + ((lane >> 4) << 3);
    int brow = (lane & 15) * WS;
    int bn   = (lane >> 4) << 3;

#pragma unroll
    for (int kt = 0; kt < 8; kt++) {
        uint32_t a0, a1, a2, a3;
        ldsm4(sptr(A + aoff + kt * 16), a0, a1, a2, a3);
#pragma unroll
        for (int jj = 0; jj < 4; jj++) {
            int nj = nbase + jj * 16;
            uint32_t b0, b1, b2, b3;
            ldsm4t(sptr(B + kt * 16 * WS + brow + nj + bn), b0, b1, b2, b3);
            mma16816(acc[2 * jj],     a0, a1, a2, a3, b0, b1);
            mma16816(acc[2 * jj + 1], a0, a1, a2, a3, b2, b3);
        }
    }
}

// ---------------- fused GIN layer (persistent grid-stride, fp16, optional fused pool) ----------------
// smem: W1 (PLANE) + W2 (PLANE) + A (TMWS) + T (TMWS) = 52224 elems = 104448 B -> 2 blocks/SM
#define OFF_A (2 * PLANE)
#define OFF_T (2 * PLANE + TMWS)
#define SMEM_ELEMS (2 * PLANE + 2 * TMWS)

extern __shared__ __half sb[];

__global__ __launch_bounds__(256) void k_layer(
    const __half* __restrict__ A, const float* __restrict__ vscal,
    const float* __restrict__ W1v,
    const __half* __restrict__ W1, const float* __restrict__ b1,
    const __half* __restrict__ W2, const float* __restrict__ b2,
    __half* __restrict__ Out,
    const int* __restrict__ comp, float* __restrict__ outPool,
    int nrows, int mode) {

    __shared__ float sv[TM];
    __shared__ float spool[HN];
    int tid  = threadIdx.x;
    int lane = tid & 31;
    int w    = tid >> 5;
    int mrow0 = (w >> 1) * 16;
    int nbase = (w & 1) * 64;

    __half* sW1 = sb;
    __half* sW2 = sb + PLANE;
    __half* sA  = sb + OFF_A;
    __half* sT  = sb + OFF_T;

    const int U4 = PLANE * 2 / 16;
    for (int i = tid; i < U4; i += 256) {
        ((uint4*)sW2)[i] = ((const uint4*)W2)[i];
        if (mode != 0) ((uint4*)sW1)[i] = ((const uint4*)W1)[i];
    }

    int ntiles = (nrows + TM - 1) / TM;
    for (int t = blockIdx.x; t < ntiles; t += gridDim.x) {
        int row0 = t * TM;
        int tr = nrows - row0; if (tr > TM) tr = TM;
        __syncthreads();

        if (mode == 0) {
            if (tid < TM) sv[tid] = (tid < tr) ? vscal[row0 + tid] : 0.f;
            __syncthreads();
            for (int i = tid; i < TM * HN; i += 256) {
                int r = i >> 7, c = i & 127;
                float v = fmaxf(fmaf(sv[r], __ldg(W1v + c), __ldg(b1 + c)), 0.f);
                sT[r * WS + c] = __float2half_rn(v);
            }
            __syncthreads();
        } else {
            if (mode == 2 && tid < HN) spool[tid] = 0.f;
            // load A tile (fp16, 8 elems per uint4)
            for (int i = tid; i < TM * HN / 8; i += 256) {
                int e = i * 8, r = e >> 7, c = e & 127;
                uint4 v = make_uint4(0u, 0u, 0u, 0u);
                if (r < tr) v = __ldg((const uint4*)(A + (size_t)(row0 + r) * HN + c));
                *(uint4*)(sA + r * WS + c) = v;
            }
            __syncthreads();

            float acc[8][4];
            mma_phase(sA, sW1, mrow0, nbase, lane, acc);

            int r0 = mrow0 + (lane >> 2);
#pragma unroll
            for (int j = 0; j < 8; j++) {
                int c = nbase + 8 * j + (lane & 3) * 2;
                float bx = __ldg(b1 + c), by = __ldg(b1 + c + 1);
                *(__half2*)(sT + r0 * WS + c) =
                    __floats2half2_rn(fmaxf(acc[j][0] + bx, 0.f), fmaxf(acc[j][1] + by, 0.f));
                *(__half2*)(sT + (r0 + 8) * WS + c) =
                    __floats2half2_rn(fmaxf(acc[j][2] + bx, 0.f), fmaxf(acc[j][3] + by, 0.f));
            }
            __syncthreads();
        }

        // phase 2: relu(T @ W2 + b2)
        float acc[8][4];
        mma_phase(sT, sW2, mrow0, nbase, lane, acc);

        int r0 = mrow0 + (lane >> 2);
        if (mode == 2) {
            int gfirst = __ldg(comp + row0);
            int glast  = __ldg(comp + row0 + tr - 1);
            if (gfirst == glast) {
                // fast path: whole tile pools into one graph; warp shfl column-reduce
#pragma unroll
                for (int j = 0; j < 8; j++) {
                    int c = nbase + 8 * j + (lane & 3) * 2;
                    float bx = __ldg(b2 + c), by = __ldg(b2 + c + 1);
                    float v0 = 0.f, v1 = 0.f;
                    if (r0 < tr)     { v0 += fmaxf(acc[j][0] + bx, 0.f); v1 += fmaxf(acc[j][1] + by, 0.f); }
                    if (r0 + 8 < tr) { v0 += fmaxf(acc[j][2] + bx, 0.f); v1 += fmaxf(acc[j][3] + by, 0.f); }
#pragma unroll
                    for (int o = 4; o <= 16; o <<= 1) {
                        v0 += __shfl_xor_sync(0xffffffffu, v0, o);
                        v1 += __shfl_xor_sync(0xffffffffu, v1, o);
                    }
                    if (lane < 4) {
                        atomicAdd(&spool[c], v0);
                        atomicAdd(&spool[c + 1], v1);
                    }
                }
                __syncthreads();
                if (tid < HN) atomicAdd(outPool + (size_t)gfirst * HN + tid, spool[tid]);
            } else {
                // boundary tile (rare): per-element global atomics
#pragma unroll
                for (int j = 0; j < 8; j++) {
                    int c = nbase + 8 * j + (lane & 3) * 2;
                    float bx = __ldg(b2 + c), by = __ldg(b2 + c + 1);
                    if (r0 < tr) {
                        int g = __ldg(comp + row0 + r0);
                        atomicAdd(outPool + (size_t)g * HN + c,     fmaxf(acc[j][0] + bx, 0.f));
                        atomicAdd(outPool + (size_t)g * HN + c + 1, fmaxf(acc[j][1] + by, 0.f));
                    }
                    if (r0 + 8 < tr) {
                        int g = __ldg(comp + row0 + r0 + 8);
                        atomicAdd(outPool + (size_t)g * HN + c,     fmaxf(acc[j][2] + bx, 0.f));
                        atomicAdd(outPool + (size_t)g * HN + c + 1, fmaxf(acc[j][3] + by, 0.f));
                    }
                }
            }
        } else {
#pragma unroll
            for (int j = 0; j < 8; j++) {
                int c = nbase + 8 * j + (lane & 3) * 2;
                float bx = __ldg(b2 + c), by = __ldg(b2 + c + 1);
                int gr0 = row0 + r0, gr1 = gr0 + 8;
                if (gr0 < nrows)
                    *(__half2*)(Out + (size_t)gr0 * HN + c) =
                        __floats2half2_rn(fmaxf(acc[j][0] + bx, 0.f), fmaxf(acc[j][1] + by, 0.f));
                if (gr1 < nrows)
                    *(__half2*)(Out + (size_t)gr1 * HN + c) =
                        __floats2half2_rn(fmaxf(acc[j][2] + bx, 0.f), fmaxf(acc[j][3] + by, 0.f));
            }
        }
    }
}

// ---------------- launch ----------------
extern "C" void kernel_launch(void* const* d_in, const int* in_sizes, int n_in,
                              void* d_out, int out_size) {
    const float* x     = (const float*)d_in[0];
    const void*  ei    = d_in[1];
    const void*  n2s   = d_in[2];
    const void*  s2g_i = d_in[3];
    const float* c1W1  = (const float*)d_in[4];
    const float* c1b1  = (const float*)d_in[5];
    const float* c1W2  = (const float*)d_in[6];
    const float* c1b2  = (const float*)d_in[7];
    const float* cW1   = (const float*)d_in[8];
    const float* cb1   = (const float*)d_in[9];
    const float* cW2   = (const float*)d_in[10];
    const float* cb2   = (const float*)d_in[11];

    int N = in_sizes[0];
    int E = in_sizes[1] / 2;
    int G = out_size / HN;

    __half *hA, *hB, *wh;
    float *agg0;
    int *eiX, *comp, *deg, *offs, *cursor, *csr;
    cudaGetSymbolAddress((void**)&hA,     g_hA);
    cudaGetSymbolAddress((void**)&hB,     g_hB);
    cudaGetSymbolAddress((void**)&agg0,   g_agg0);
    cudaGetSymbolAddress((void**)&eiX,    g_ei);
    cudaGetSymbolAddress((void**)&comp,   g_comp);
    cudaGetSymbolAddress((void**)&deg,    g_deg);
    cudaGetSymbolAddress((void**)&offs,   g_offs);
    cudaGetSymbolAddress((void**)&cursor, g_cursor);
    cudaGetSymbolAddress((void**)&csr,    g_csr);
    cudaGetSymbolAddress((void**)&wh,     g_whalf);

    const int SMEM = SMEM_ELEMS * 2;   // 104448 B -> 2 blocks/SM
    cudaFuncSetAttribute(k_layer, cudaFuncAttributeMaxDynamicSharedMemorySize, SMEM);

    // init (parallel detect), zero deg/cursor, normalize indices
    k_init<<<1, 64>>>((const unsigned long long*)ei);
    k_zero2i<<<(N + 255) / 256, 256>>>(deg, cursor, N);
    k_convert_ei<<<(2 * E + 255) / 256, 256>>>(ei, eiX, deg, E);
    k_comp2<<<(N + 255) / 256, 256>>>(n2s, s2g_i, comp, N);

    // all 5 weight matrices -> fp16 planes (one launch)
    k_cvtW5<<<(5 * HN * HN + 255) / 256, 256>>>(c1W2, cW1, cW2, wh);

    // CSR build (dst-major)
    k_scan<<<1, 1024>>>(deg, offs, N);
    k_scatter<<<(E + 255) / 256, 256>>>(eiX, eiX + E, offs, cursor, csr, E);

    int ablocks0 = (N * 32 + 255) / 256;       // warp-per-node (k_agg0)
    int ablocks  = (N * 16 + 255) / 256;       // half-warp-per-node (k_agg_csr)
    const int LGRID = 296;   // 2 blocks/SM

    // layer 1: scalar agg + fused expansion/MMA -> hB
    k_agg0<<<ablocks0, 256>>>(offs, csr, x, agg0, N);
    k_layer<<<LGRID, 256, SMEM>>>(nullptr, agg0, c1W1, nullptr, c1b1,
                                  wh + 0 * PLANE, c1b2, hB,
                                  nullptr, nullptr, N, 0);

    // layer 2: agg + dual MMA -> hB
    k_agg_csr<<<ablocks, 256>>>(offs, csr, hB, hA, N);
    k_layer<<<LGRID, 256, SMEM>>>(hA, nullptr, nullptr,
                                  wh + 1 * PLANE, cb1, wh + 2 * PLANE, cb2, hB,
                                  nullptr, nullptr, N, 1);

    // layer 3: agg + dual MMA with fused pooling -> d_out
    k_agg_csr<<<ablocks, 256>>>(offs, csr, hB, hA, N);
    k_zero4<<<((G * HN / 4) + 255) / 256, 256>>>((float*)d_out, G * HN / 4);
    k_layer<<<LGRID, 256, SMEM>>>(hA, nullptr, nullptr,
                                  wh + 3 * PLANE, cb1 + HN, wh + 4 * PLANE, cb2 + HN,
                                  nullptr, comp, (float*)d_out, N, 2);
}

// round 16
// speedup vs baseline: 1.3117x; 1.0487x over previous
#include <cuda_runtime.h>
#include <cuda_fp16.h>
#include <cstdint>

#define HN   128
#define MAXN 100000
#define MAXE 1600000
#define MAXS 10000
#define TM   64
#define WS   136            // padded fp16 plane stride (ldsm conflict-free)
#define PLANE (HN * WS)     // 17408
#define TMWS  (TM * WS)     // 8704

// ---------------- scratch (static device globals; no allocation) ----------------
__device__ __align__(16) __half g_hA[(size_t)MAXN * HN];
__device__ __align__(16) __half g_hB[(size_t)MAXN * HN];
__device__ float g_agg0[MAXN];
__device__ int   g_ei[2 * MAXE];
__device__ int   g_comp[MAXN];
__device__ int   g_deg[MAXN];
__device__ int   g_offs[MAXN + 1];
__device__ int   g_cursor[MAXN];
__device__ int   g_csr[MAXE];
__device__ int   g_is64;
__device__ __align__(16) __half g_whalf[5 * PLANE];   // 5 matrices, one fp16 plane each

// ---------------- helpers ----------------
__device__ __forceinline__ uint32_t sptr(const void* p) {
    return (uint32_t)__cvta_generic_to_shared(p);
}
__device__ __forceinline__ void ldsm4(uint32_t a, uint32_t& r0, uint32_t& r1,
                                      uint32_t& r2, uint32_t& r3) {
    asm volatile("ldmatrix.sync.aligned.m8n8.x4.shared.b16 {%0,%1,%2,%3},[%4];"
                 : "=r"(r0), "=r"(r1), "=r"(r2), "=r"(r3) : "r"(a));
}
__device__ __forceinline__ void ldsm4t(uint32_t a, uint32_t& r0, uint32_t& r1,
                                       uint32_t& r2, uint32_t& r3) {
    asm volatile("ldmatrix.sync.aligned.m8n8.x4.trans.shared.b16 {%0,%1,%2,%3},[%4];"
                 : "=r"(r0), "=r"(r1), "=r"(r2), "=r"(r3) : "r"(a));
}
__device__ __forceinline__ void mma16816(float* c, uint32_t a0, uint32_t a1, uint32_t a2,
                                         uint32_t a3, uint32_t b0, uint32_t b1) {
    asm volatile(
        "mma.sync.aligned.m16n8k16.row.col.f32.f16.f16.f32 "
        "{%0,%1,%2,%3},{%4,%5,%6,%7},{%8,%9},{%0,%1,%2,%3};"
        : "+f"(c[0]), "+f"(c[1]), "+f"(c[2]), "+f"(c[3])
        : "r"(a0), "r"(a1), "r"(a2), "r"(a3), "r"(b0), "r"(b1));
}
// accumulate 8 fp16 (uint4) into 8 fp32
__device__ __forceinline__ void addh4(float* a, uint4 v) {
    float2 f0 = __half22float2(*(__half2*)&v.x);
    float2 f1 = __half22float2(*(__half2*)&v.y);
    float2 f2 = __half22float2(*(__half2*)&v.z);
    float2 f3 = __half22float2(*(__half2*)&v.w);
    a[0] += f0.x; a[1] += f0.y; a[2] += f1.x; a[3] += f1.y;
    a[4] += f2.x; a[5] += f2.y; a[6] += f3.x; a[7] += f3.y;
}

// ---------------- init: parallel dtype detect ----------------
__global__ void k_init(const unsigned long long* __restrict__ p) {
    int lane = threadIdx.x;
    unsigned long long v = (lane < 64) ? p[lane] : 0ull;
    unsigned any_hi = __ballot_sync(0xffffffffu, (lane < 64) && (v >> 32));
    __shared__ int hi;
    if (threadIdx.x == 0) hi = 0;
    __syncthreads();
    if (any_hi && (lane & 31) == 0) atomicOr(&hi, 1);
    __syncthreads();
    if (threadIdx.x == 0) g_is64 = hi ? 0 : 1;
}

// ---------------- merged setup: zero deg/cursor + comp + W convert ----------------
__global__ void k_setup(const void* __restrict__ n2s, const void* __restrict__ s2g,
                        int* __restrict__ comp, int* __restrict__ deg,
                        int* __restrict__ cursor,
                        const float* __restrict__ c1W2, const float* __restrict__ cW1,
                        const float* __restrict__ cW2, __half* __restrict__ wh, int N) {
    int i = blockIdx.x * blockDim.x + threadIdx.x;
    if (i < N) {
        deg[i] = 0;
        cursor[i] = 0;
        int s, g;
        if (g_is64) {
            s = (int)(((const long long*)n2s)[i]);
            g = (int)(((const long long*)s2g)[s]);
        } else {
            s = ((const int*)n2s)[i];
            g = ((const int*)s2g)[s];
        }
        comp[i] = g;
    } else {
        int j = i - N;
        if (j < 5 * HN * HN) {
            int m = j / (HN * HN), r = j % (HN * HN);
            const float* src = (m == 0) ? c1W2 : (m == 1) ? cW1 : (m == 2) ? cW2
                             : (m == 3) ? (cW1 + HN * HN) : (cW2 + HN * HN);
            int k = r >> 7, n = r & 127;
            wh[(size_t)m * PLANE + k * WS + n] = __float2half_rn(src[r]);
        }
    }
}

// convert both halves of edge_index; histogram degrees from the dst half
__global__ void k_convert_ei(const void* __restrict__ in, int* __restrict__ out,
                             int* __restrict__ deg, int E) {
    int i = blockIdx.x * blockDim.x + threadIdx.x;
    if (i >= 2 * E) return;
    int v;
    if (g_is64) v = (int)(((const long long*)in)[i]);
    else        v = ((const int*)in)[i];
    out[i] = v;
    if (i >= E) atomicAdd(deg + v, 1);
}

// ---------------- utility ----------------
__global__ void k_zero4(float* __restrict__ p, int n4) {
    int i = blockIdx.x * blockDim.x + threadIdx.x;
    if (i < n4) ((float4*)p)[i] = make_float4(0.f, 0.f, 0.f, 0.f);
}

// ---------------- CSR build ----------------
__global__ void k_scan(const int* __restrict__ deg, int* __restrict__ offs, int n) {
    __shared__ int sums[1024];
    int tid = threadIdx.x;
    int chunk = (n + 1023) / 1024;
    int start = tid * chunk;
    int end   = start + chunk; if (end > n) end = n;
    int s = 0;
    for (int i = start; i < end; i++) s += deg[i];
    sums[tid] = s;
    __syncthreads();
    for (int off = 1; off < 1024; off <<= 1) {
        int v = 0;
        if (tid >= off) v = sums[tid - off];
        __syncthreads();
        if (tid >= off) sums[tid] += v;
        __syncthreads();
    }
    int run = (tid == 0) ? 0 : sums[tid - 1];
    for (int i = start; i < end; i++) { offs[i] = run; run += deg[i]; }
    if (end == n) offs[n] = run;
}
__global__ void k_scatter(const int* __restrict__ src, const int* __restrict__ dst,
                          const int* __restrict__ offs, int* __restrict__ cursor,
                          int* __restrict__ csr, int E) {
    int e = blockIdx.x * blockDim.x + threadIdx.x;
    if (e >= E) return;
    int d = dst[e];
    int p = atomicAdd(cursor + d, 1);
    csr[offs[d] + p] = src[e];
}

// ---------------- layer-1 scalar aggregation ----------------
__global__ void k_agg0(const int* __restrict__ offs, const int* __restrict__ csr,
                       const float* __restrict__ x, float* __restrict__ agg, int N) {
    int warp = (blockIdx.x * blockDim.x + threadIdx.x) >> 5;
    int lane = threadIdx.x & 31;
    if (warp >= N) return;
    int s = offs[warp], e = offs[warp + 1];
    float acc = 0.f;
    for (int i = s + lane; i < e; i += 32) acc += __ldg(x + csr[i]);
#pragma unroll
    for (int o = 16; o; o >>= 1) acc += __shfl_xor_sync(0xffffffffu, acc, o);
    if (lane == 0) agg[warp] = acc + x[warp];
}

// ---------------- fp16 vector aggregation incl. self (half-warp per node, uint4) ----------------
__global__ __launch_bounds__(256) void k_agg_csr(
    const int* __restrict__ offs, const int* __restrict__ csr,
    const __half* __restrict__ h, __half* __restrict__ out, int N) {
    int hw = (blockIdx.x * blockDim.x + threadIdx.x) >> 4;   // half-warp = node
    int ln = threadIdx.x & 15;                               // 16 lanes x 16B = 256B row
    if (hw >= N) return;
    int s = __ldg(offs + hw), e = __ldg(offs + hw + 1);
    float acc[8] = {0.f, 0.f, 0.f, 0.f, 0.f, 0.f, 0.f, 0.f};
    addh4(acc, __ldg(((const uint4*)(h + (size_t)hw * HN)) + ln));   // self
    int i = s;
#pragma unroll 1
    for (; i + 8 <= e; i += 8) {
        int idx[8];
#pragma unroll
        for (int u = 0; u < 8; u++) idx[u] = __ldg(csr + i + u);
        uint4 v[8];
#pragma unroll
        for (int u = 0; u < 8; u++)
            v[u] = __ldg(((const uint4*)(h + (size_t)idx[u] * HN)) + ln);
#pragma unroll
        for (int u = 0; u < 8; u++) addh4(acc, v[u]);
    }
    for (; i < e; i++)
        addh4(acc, __ldg(((const uint4*)(h + (size_t)__ldg(csr + i) * HN)) + ln));
    uint4 o;
    __half2 p0 = __floats2half2_rn(acc[0], acc[1]);
    __half2 p1 = __floats2half2_rn(acc[2], acc[3]);
    __half2 p2 = __floats2half2_rn(acc[4], acc[5]);
    __half2 p3 = __floats2half2_rn(acc[6], acc[7]);
    o.x = *(uint32_t*)&p0; o.y = *(uint32_t*)&p1;
    o.z = *(uint32_t*)&p2; o.w = *(uint32_t*)&p3;
    ((uint4*)(out + (size_t)hw * HN))[ln] = o;
}

// ---------------- MMA: warp m32 x n32 tile of A[64,128] @ W[128,128] ----------------
// acc[mi][nj][c]: mi in {0,1} (m16 frags), nj in {0..3} (n8 frags)
__device__ __forceinline__ void mma_phase(
    const __half* A, const __half* B,
    int mrow0, int nbase, int lane, float acc[2][4][4]) {
#pragma unroll
    for (int mi = 0; mi < 2; mi++)
#pragma unroll
        for (int nj = 0; nj < 4; nj++)
#pragma unroll
            for (int c = 0; c < 4; c++) acc[mi][nj][c] = 0.f;

    int arow = mrow0 + (lane & 15);
    int acol = (lane >> 4) << 3;
    int brow = (lane & 15) * WS;
    int bn   = (lane >> 4) << 3;

#pragma unroll
    for (int kt = 0; kt < 8; kt++) {
        uint32_t a[2][4];
#pragma unroll
        for (int mi = 0; mi < 2; mi++)
            ldsm4(sptr(A + (arow + mi * 16) * WS + kt * 16 + acol),
                  a[mi][0], a[mi][1], a[mi][2], a[mi][3]);
#pragma unroll
        for (int ni = 0; ni < 2; ni++) {
            uint32_t b0, b1, b2, b3;
            ldsm4t(sptr(B + kt * 16 * WS + brow + nbase + ni * 16 + bn), b0, b1, b2, b3);
#pragma unroll
            for (int mi = 0; mi < 2; mi++) {
                mma16816(acc[mi][2 * ni],     a[mi][0], a[mi][1], a[mi][2], a[mi][3], b0, b1);
                mma16816(acc[mi][2 * ni + 1], a[mi][0], a[mi][1], a[mi][2], a[mi][3], b2, b3);
            }
        }
    }
}

// ---------------- fused GIN layer (persistent grid-stride, fp16, optional fused pool) ----------------
// smem: W1 (PLANE) + W2 (PLANE) + A (TMWS) + T (TMWS) = 52224 elems = 104448 B -> 2 blocks/SM
#define OFF_A (2 * PLANE)
#define OFF_T (2 * PLANE + TMWS)
#define SMEM_ELEMS (2 * PLANE + 2 * TMWS)

extern __shared__ __half sb[];

__global__ __launch_bounds__(256) void k_layer(
    const __half* __restrict__ A, const float* __restrict__ vscal,
    const float* __restrict__ W1v,
    const __half* __restrict__ W1, const float* __restrict__ b1,
    const __half* __restrict__ W2, const float* __restrict__ b2,
    __half* __restrict__ Out,
    const int* __restrict__ comp, float* __restrict__ outPool,
    int nrows, int mode) {

    __shared__ float sv[TM];
    __shared__ float spool[HN];
    int tid  = threadIdx.x;
    int lane = tid & 31;
    int w    = tid >> 5;
    int mrow0 = (w >> 2) * 32;   // 2 m-groups of 32 rows
    int nbase = (w & 3) * 32;    // 4 n-groups of 32 cols

    __half* sW1 = sb;
    __half* sW2 = sb + PLANE;
    __half* sA  = sb + OFF_A;
    __half* sT  = sb + OFF_T;

    const int U4 = PLANE * 2 / 16;
    for (int i = tid; i < U4; i += 256) {
        ((uint4*)sW2)[i] = ((const uint4*)W2)[i];
        if (mode != 0) ((uint4*)sW1)[i] = ((const uint4*)W1)[i];
    }

    int ntiles = (nrows + TM - 1) / TM;
    for (int t = blockIdx.x; t < ntiles; t += gridDim.x) {
        int row0 = t * TM;
        int tr = nrows - row0; if (tr > TM) tr = TM;
        __syncthreads();

        if (mode == 0) {
            if (tid < TM) sv[tid] = (tid < tr) ? vscal[row0 + tid] : 0.f;
            __syncthreads();
            for (int i = tid; i < TM * HN; i += 256) {
                int r = i >> 7, c = i & 127;
                float v = fmaxf(fmaf(sv[r], __ldg(W1v + c), __ldg(b1 + c)), 0.f);
                sT[r * WS + c] = __float2half_rn(v);
            }
            __syncthreads();
        } else {
            if (mode == 2 && tid < HN) spool[tid] = 0.f;
            // load A tile (fp16, 8 elems per uint4)
            for (int i = tid; i < TM * HN / 8; i += 256) {
                int e = i * 8, r = e >> 7, c = e & 127;
                uint4 v = make_uint4(0u, 0u, 0u, 0u);
                if (r < tr) v = __ldg((const uint4*)(A + (size_t)(row0 + r) * HN + c));
                *(uint4*)(sA + r * WS + c) = v;
            }
            __syncthreads();

            float acc[2][4][4];
            mma_phase(sA, sW1, mrow0, nbase, lane, acc);

#pragma unroll
            for (int mi = 0; mi < 2; mi++) {
                int r0 = mrow0 + mi * 16 + (lane >> 2);
#pragma unroll
                for (int nj = 0; nj < 4; nj++) {
                    int c = nbase + nj * 8 + (lane & 3) * 2;
                    float bx = __ldg(b1 + c), by = __ldg(b1 + c + 1);
                    *(__half2*)(sT + r0 * WS + c) =
                        __floats2half2_rn(fmaxf(acc[mi][nj][0] + bx, 0.f),
                                          fmaxf(acc[mi][nj][1] + by, 0.f));
                    *(__half2*)(sT + (r0 + 8) * WS + c) =
                        __floats2half2_rn(fmaxf(acc[mi][nj][2] + bx, 0.f),
                                          fmaxf(acc[mi][nj][3] + by, 0.f));
                }
            }
            __syncthreads();
        }

        // phase 2: relu(T @ W2 + b2)
        float acc[2][4][4];
        mma_phase(sT, sW2, mrow0, nbase, lane, acc);

        if (mode == 2) {
            int gfirst = __ldg(comp + row0);
            int glast  = __ldg(comp + row0 + tr - 1);
            if (gfirst == glast) {
                // fast path: whole tile pools into one graph; warp shfl column-reduce
#pragma unroll
                for (int mi = 0; mi < 2; mi++) {
                    int r0 = mrow0 + mi * 16 + (lane >> 2);
#pragma unroll
                    for (int nj = 0; nj < 4; nj++) {
                        int c = nbase + nj * 8 + (lane & 3) * 2;
                        float bx = __ldg(b2 + c), by = __ldg(b2 + c + 1);
                        float v0 = 0.f, v1 = 0.f;
                        if (r0 < tr)     { v0 += fmaxf(acc[mi][nj][0] + bx, 0.f);
                                           v1 += fmaxf(acc[mi][nj][1] + by, 0.f); }
                        if (r0 + 8 < tr) { v0 += fmaxf(acc[mi][nj][2] + bx, 0.f);
                                           v1 += fmaxf(acc[mi][nj][3] + by, 0.f); }
#pragma unroll
                        for (int o = 4; o <= 16; o <<= 1) {
                            v0 += __shfl_xor_sync(0xffffffffu, v0, o);
                            v1 += __shfl_xor_sync(0xffffffffu, v1, o);
                        }
                        if (lane < 4) {
                            atomicAdd(&spool[c], v0);
                            atomicAdd(&spool[c + 1], v1);
                        }
                    }
                }
                __syncthreads();
                if (tid < HN) atomicAdd(outPool + (size_t)gfirst * HN + tid, spool[tid]);
            } else {
                // boundary tile (rare): per-element global atomics
#pragma unroll
                for (int mi = 0; mi < 2; mi++) {
                    int r0 = mrow0 + mi * 16 + (lane >> 2);
#pragma unroll
                    for (int nj = 0; nj < 4; nj++) {
                        int c = nbase + nj * 8 + (lane & 3) * 2;
                        float bx = __ldg(b2 + c), by = __ldg(b2 + c + 1);
                        if (r0 < tr) {
                            int g = __ldg(comp + row0 + r0);
                            atomicAdd(outPool + (size_t)g * HN + c,
                                      fmaxf(acc[mi][nj][0] + bx, 0.f));
                            atomicAdd(outPool + (size_t)g * HN + c + 1,
                                      fmaxf(acc[mi][nj][1] + by, 0.f));
                        }
                        if (r0 + 8 < tr) {
                            int g = __ldg(comp + row0 + r0 + 8);
                            atomicAdd(outPool + (size_t)g * HN + c,
                                      fmaxf(acc[mi][nj][2] + bx, 0.f));
                            atomicAdd(outPool + (size_t)g * HN + c + 1,
                                      fmaxf(acc[mi][nj][3] + by, 0.f));
                        }
                    }
                }
            }
        } else {
#pragma unroll
            for (int mi = 0; mi < 2; mi++) {
                int r0 = mrow0 + mi * 16 + (lane >> 2);
#pragma unroll
                for (int nj = 0; nj < 4; nj++) {
                    int c = nbase + nj * 8 + (lane & 3) * 2;
                    float bx = __ldg(b2 + c), by = __ldg(b2 + c + 1);
                    int gr0 = row0 + r0, gr1 = gr0 + 8;
                    if (gr0 < nrows)
                        *(__half2*)(Out + (size_t)gr0 * HN + c) =
                            __floats2half2_rn(fmaxf(acc[mi][nj][0] + bx, 0.f),
                                              fmaxf(acc[mi][nj][1] + by, 0.f));
                    if (gr1 < nrows)
                        *(__half2*)(Out + (size_t)gr1 * HN + c) =
                            __floats2half2_rn(fmaxf(acc[mi][nj][2] + bx, 0.f),
                                              fmaxf(acc[mi][nj][3] + by, 0.f));
                }
            }
        }
    }
}

// ---------------- launch ----------------
extern "C" void kernel_launch(void* const* d_in, const int* in_sizes, int n_in,
                              void* d_out, int out_size) {
    const float* x     = (const float*)d_in[0];
    const void*  ei    = d_in[1];
    const void*  n2s   = d_in[2];
    const void*  s2g_i = d_in[3];
    const float* c1W1  = (const float*)d_in[4];
    const float* c1b1  = (const float*)d_in[5];
    const float* c1W2  = (const float*)d_in[6];
    const float* c1b2  = (const float*)d_in[7];
    const float* cW1   = (const float*)d_in[8];
    const float* cb1   = (const float*)d_in[9];
    const float* cW2   = (const float*)d_in[10];
    const float* cb2   = (const float*)d_in[11];

    int N = in_sizes[0];
    int E = in_sizes[1] / 2;
    int G = out_size / HN;

    __half *hA, *hB, *wh;
    float *agg0;
    int *eiX, *comp, *deg, *offs, *cursor, *csr;
    cudaGetSymbolAddress((void**)&hA,     g_hA);
    cudaGetSymbolAddress((void**)&hB,     g_hB);
    cudaGetSymbolAddress((void**)&agg0,   g_agg0);
    cudaGetSymbolAddress((void**)&eiX,    g_ei);
    cudaGetSymbolAddress((void**)&comp,   g_comp);
    cudaGetSymbolAddress((void**)&deg,    g_deg);
    cudaGetSymbolAddress((void**)&offs,   g_offs);
    cudaGetSymbolAddress((void**)&cursor, g_cursor);
    cudaGetSymbolAddress((void**)&csr,    g_csr);
    cudaGetSymbolAddress((void**)&wh,     g_whalf);

    const int SMEM = SMEM_ELEMS * 2;   // 104448 B -> 2 blocks/SM
    cudaFuncSetAttribute(k_layer, cudaFuncAttributeMaxDynamicSharedMemorySize, SMEM);

    // init (parallel detect), merged setup (zero + comp + W convert), index convert
    k_init<<<1, 64>>>((const unsigned long long*)ei);
    int setup_items = N + 5 * HN * HN;
    k_setup<<<(setup_items + 255) / 256, 256>>>(n2s, s2g_i, comp, deg, cursor,
                                                c1W2, cW1, cW2, wh, N);
    k_convert_ei<<<(2 * E + 255) / 256, 256>>>(ei, eiX, deg, E);

    // CSR build (dst-major)
    k_scan<<<1, 1024>>>(deg, offs, N);
    k_scatter<<<(E + 255) / 256, 256>>>(eiX, eiX + E, offs, cursor, csr, E);

    int ablocks0 = (N * 32 + 255) / 256;       // warp-per-node (k_agg0)
    int ablocks  = (N * 16 + 255) / 256;       // half-warp-per-node (k_agg_csr)
    const int LGRID = 296;   // 2 blocks/SM

    // layer 1: scalar agg + fused expansion/MMA -> hB
    k_agg0<<<ablocks0, 256>>>(offs, csr, x, agg0, N);
    k_layer<<<LGRID, 256, SMEM>>>(nullptr, agg0, c1W1, nullptr, c1b1,
                                  wh + 0 * PLANE, c1b2, hB,
                                  nullptr, nullptr, N, 0);

    // layer 2: agg + dual MMA -> hB
    k_agg_csr<<<ablocks, 256>>>(offs, csr, hB, hA, N);
    k_layer<<<LGRID, 256, SMEM>>>(hA, nullptr, nullptr,
                                  wh + 1 * PLANE, cb1, wh + 2 * PLANE, cb2, hB,
                                  nullptr, nullptr, N, 1);

    // layer 3: agg + dual MMA with fused pooling -> d_out
    k_agg_csr<<<ablocks, 256>>>(offs, csr, hB, hA, N);
    k_zero4<<<((G * HN / 4) + 255) / 256, 256>>>((float*)d_out, G * HN / 4);
    k_layer<<<LGRID, 256, SMEM>>>(hA, nullptr, nullptr,
                                  wh + 3 * PLANE, cb1 + HN, wh + 4 * PLANE, cb2 + HN,
                                  nullptr, comp, (float*)d_out, N, 2);
}

// round 17
// speedup vs baseline: 1.8046x; 1.3757x over previous
#include <cuda_runtime.h>
#include <cuda_fp16.h>
#include <cstdint>

#define HN   128
#define MAXN 100000
#define MAXE 1600000
#define MAXS 10000
#define TM   64
#define WS   136            // padded fp16 plane stride (ldsm conflict-free)
#define PLANE (HN * WS)     // 17408
#define TMWS  (TM * WS)     // 8704
#define SCHUNK 1024         // scan chunk per block
#define SBLOCKS ((MAXN + SCHUNK - 1) / SCHUNK)   // 98

// ---------------- scratch (static device globals; no allocation) ----------------
__device__ __align__(16) __half g_hA[(size_t)MAXN * HN];
__device__ __align__(16) __half g_hB[(size_t)MAXN * HN];
__device__ float g_agg0[MAXN];
__device__ int   g_ei[2 * MAXE];
__device__ int   g_comp[MAXN];
__device__ int   g_deg[MAXN];
__device__ int   g_offs[MAXN + 1];
__device__ int   g_cursor[MAXN];
__device__ int   g_csr[MAXE];
__device__ int   g_bsum[SBLOCKS];
__device__ int   g_boffs[SBLOCKS];
__device__ int   g_is64;
__device__ __align__(16) __half g_whalf[5 * PLANE];   // 5 matrices, one fp16 plane each

// ---------------- helpers ----------------
__device__ __forceinline__ uint32_t sptr(const void* p) {
    return (uint32_t)__cvta_generic_to_shared(p);
}
__device__ __forceinline__ void ldsm4(uint32_t a, uint32_t& r0, uint32_t& r1,
                                      uint32_t& r2, uint32_t& r3) {
    asm volatile("ldmatrix.sync.aligned.m8n8.x4.shared.b16 {%0,%1,%2,%3},[%4];"
                 : "=r"(r0), "=r"(r1), "=r"(r2), "=r"(r3) : "r"(a));
}
__device__ __forceinline__ void ldsm4t(uint32_t a, uint32_t& r0, uint32_t& r1,
                                       uint32_t& r2, uint32_t& r3) {
    asm volatile("ldmatrix.sync.aligned.m8n8.x4.trans.shared.b16 {%0,%1,%2,%3},[%4];"
                 : "=r"(r0), "=r"(r1), "=r"(r2), "=r"(r3) : "r"(a));
}
__device__ __forceinline__ void mma16816(float* c, uint32_t a0, uint32_t a1, uint32_t a2,
                                         uint32_t a3, uint32_t b0, uint32_t b1) {
    asm volatile(
        "mma.sync.aligned.m16n8k16.row.col.f32.f16.f16.f32 "
        "{%0,%1,%2,%3},{%4,%5,%6,%7},{%8,%9},{%0,%1,%2,%3};"
        : "+f"(c[0]), "+f"(c[1]), "+f"(c[2]), "+f"(c[3])
        : "r"(a0), "r"(a1), "r"(a2), "r"(a3), "r"(b0), "r"(b1));
}
// accumulate 8 fp16 (uint4) into 8 fp32
__device__ __forceinline__ void addh4(float* a, uint4 v) {
    float2 f0 = __half22float2(*(__half2*)&v.x);
    float2 f1 = __half22float2(*(__half2*)&v.y);
    float2 f2 = __half22float2(*(__half2*)&v.z);
    float2 f3 = __half22float2(*(__half2*)&v.w);
    a[0] += f0.x; a[1] += f0.y; a[2] += f1.x; a[3] += f1.y;
    a[4] += f2.x; a[5] += f2.y; a[6] += f3.x; a[7] += f3.y;
}

// ---------------- init: parallel dtype detect ----------------
__global__ void k_init(const unsigned long long* __restrict__ p) {
    int lane = threadIdx.x;
    unsigned long long v = (lane < 64) ? p[lane] : 0ull;
    unsigned any_hi = __ballot_sync(0xffffffffu, (lane < 64) && (v >> 32));
    __shared__ int hi;
    if (threadIdx.x == 0) hi = 0;
    __syncthreads();
    if (any_hi && (lane & 31) == 0) atomicOr(&hi, 1);
    __syncthreads();
    if (threadIdx.x == 0) g_is64 = hi ? 0 : 1;
}

// ---------------- merged setup: zero deg/cursor + comp + W convert ----------------
__global__ void k_setup(const void* __restrict__ n2s, const void* __restrict__ s2g,
                        int* __restrict__ comp, int* __restrict__ deg,
                        int* __restrict__ cursor,
                        const float* __restrict__ c1W2, const float* __restrict__ cW1,
                        const float* __restrict__ cW2, __half* __restrict__ wh, int N) {
    int i = blockIdx.x * blockDim.x + threadIdx.x;
    if (i < N) {
        deg[i] = 0;
        cursor[i] = 0;
        int s, g;
        if (g_is64) {
            s = (int)(((const long long*)n2s)[i]);
            g = (int)(((const long long*)s2g)[s]);
        } else {
            s = ((const int*)n2s)[i];
            g = ((const int*)s2g)[s];
        }
        comp[i] = g;
    } else {
        int j = i - N;
        if (j < 5 * HN * HN) {
            int m = j / (HN * HN), r = j % (HN * HN);
            const float* src = (m == 0) ? c1W2 : (m == 1) ? cW1 : (m == 2) ? cW2
                             : (m == 3) ? (cW1 + HN * HN) : (cW2 + HN * HN);
            int k = r >> 7, n = r & 127;
            wh[(size_t)m * PLANE + k * WS + n] = __float2half_rn(src[r]);
        }
    }
}

// convert both halves of edge_index; histogram degrees from the dst half
__global__ void k_convert_ei(const void* __restrict__ in, int* __restrict__ out,
                             int* __restrict__ deg, int E) {
    int i = blockIdx.x * blockDim.x + threadIdx.x;
    if (i >= 2 * E) return;
    int v;
    if (g_is64) v = (int)(((const long long*)in)[i]);
    else        v = ((const int*)in)[i];
    out[i] = v;
    if (i >= E) atomicAdd(deg + v, 1);
}

// ---------------- utility ----------------
__global__ void k_zero4(float* __restrict__ p, int n4) {
    int i = blockIdx.x * blockDim.x + threadIdx.x;
    if (i < n4) ((float4*)p)[i] = make_float4(0.f, 0.f, 0.f, 0.f);
}

// ---------------- CSR build: 3-pass multi-block scan ----------------
// pass 1: per-block reduce of a 1024-elem chunk
__global__ void k_scan1(const int* __restrict__ deg, int* __restrict__ bsum, int n) {
    __shared__ int sh[256];
    int b = blockIdx.x, t = threadIdx.x;
    int base = b * SCHUNK + t * 4;
    int s = 0;
#pragma unroll
    for (int k = 0; k < 4; k++) {
        int i = base + k;
        if (i < n) s += deg[i];
    }
    sh[t] = s;
    __syncthreads();
    for (int off = 128; off; off >>= 1) {
        if (t < off) sh[t] += sh[t + off];
        __syncthreads();
    }
    if (t == 0) bsum[b] = sh[0];
}
// pass 2: exclusive scan of block sums (nb <= 128); writes offs[n] = total
__global__ void k_scan2(const int* __restrict__ bsum, int* __restrict__ boffs,
                        int* __restrict__ offs, int nb, int n) {
    __shared__ int sh[128];
    int t = threadIdx.x;
    int v = (t < nb) ? bsum[t] : 0;
    sh[t] = v;
    __syncthreads();
    for (int off = 1; off < 128; off <<= 1) {
        int u = (t >= off) ? sh[t - off] : 0;
        __syncthreads();
        sh[t] += u;
        __syncthreads();
    }
    if (t < nb) boffs[t] = sh[t] - v;          // exclusive prefix
    if (t == nb - 1) offs[n] = sh[t];          // total
}
// pass 3: per-block exclusive scan + global offset
__global__ void k_scan3(const int* __restrict__ deg, const int* __restrict__ boffs,
                        int* __restrict__ offs, int n) {
    __shared__ int sh[256];
    int b = blockIdx.x, t = threadIdx.x;
    int base = b * SCHUNK + t * 4;
    int d[4];
    int s = 0;
#pragma unroll
    for (int k = 0; k < 4; k++) {
        int i = base + k;
        d[k] = (i < n) ? deg[i] : 0;
        s += d[k];
    }
    sh[t] = s;
    __syncthreads();
    for (int off = 1; off < 256; off <<= 1) {
        int u = (t >= off) ? sh[t - off] : 0;
        __syncthreads();
        sh[t] += u;
        __syncthreads();
    }
    int run = boffs[b] + sh[t] - s;            // exclusive prefix for this thread
#pragma unroll
    for (int k = 0; k < 4; k++) {
        int i = base + k;
        if (i < n) { offs[i] = run; run += d[k]; }
    }
}

__global__ void k_scatter(const int* __restrict__ src, const int* __restrict__ dst,
                          const int* __restrict__ offs, int* __restrict__ cursor,
                          int* __restrict__ csr, int E) {
    int e = blockIdx.x * blockDim.x + threadIdx.x;
    if (e >= E) return;
    int d = dst[e];
    int p = atomicAdd(cursor + d, 1);
    csr[offs[d] + p] = src[e];
}

// ---------------- layer-1 scalar aggregation ----------------
__global__ void k_agg0(const int* __restrict__ offs, const int* __restrict__ csr,
                       const float* __restrict__ x, float* __restrict__ agg, int N) {
    int warp = (blockIdx.x * blockDim.x + threadIdx.x) >> 5;
    int lane = threadIdx.x & 31;
    if (warp >= N) return;
    int s = offs[warp], e = offs[warp + 1];
    float acc = 0.f;
    for (int i = s + lane; i < e; i += 32) acc += __ldg(x + csr[i]);
#pragma unroll
    for (int o = 16; o; o >>= 1) acc += __shfl_xor_sync(0xffffffffu, acc, o);
    if (lane == 0) agg[warp] = acc + x[warp];
}

// ---------------- fp16 vector aggregation incl. self (half-warp per node, uint4) ----------------
__global__ __launch_bounds__(256) void k_agg_csr(
    const int* __restrict__ offs, const int* __restrict__ csr,
    const __half* __restrict__ h, __half* __restrict__ out, int N) {
    int hw = (blockIdx.x * blockDim.x + threadIdx.x) >> 4;   // half-warp = node
    int ln = threadIdx.x & 15;                               // 16 lanes x 16B = 256B row
    if (hw >= N) return;
    int s = __ldg(offs + hw), e = __ldg(offs + hw + 1);
    float acc[8] = {0.f, 0.f, 0.f, 0.f, 0.f, 0.f, 0.f, 0.f};
    addh4(acc, __ldg(((const uint4*)(h + (size_t)hw * HN)) + ln));   // self
    int i = s;
#pragma unroll 1
    for (; i + 8 <= e; i += 8) {
        int idx[8];
#pragma unroll
        for (int u = 0; u < 8; u++) idx[u] = __ldg(csr + i + u);
        uint4 v[8];
#pragma unroll
        for (int u = 0; u < 8; u++)
            v[u] = __ldg(((const uint4*)(h + (size_t)idx[u] * HN)) + ln);
#pragma unroll
        for (int u = 0; u < 8; u++) addh4(acc, v[u]);
    }
    for (; i < e; i++)
        addh4(acc, __ldg(((const uint4*)(h + (size_t)__ldg(csr + i) * HN)) + ln));
    uint4 o;
    __half2 p0 = __floats2half2_rn(acc[0], acc[1]);
    __half2 p1 = __floats2half2_rn(acc[2], acc[3]);
    __half2 p2 = __floats2half2_rn(acc[4], acc[5]);
    __half2 p3 = __floats2half2_rn(acc[6], acc[7]);
    o.x = *(uint32_t*)&p0; o.y = *(uint32_t*)&p1;
    o.z = *(uint32_t*)&p2; o.w = *(uint32_t*)&p3;
    ((uint4*)(out + (size_t)hw * HN))[ln] = o;
}

// ---------------- MMA: warp m32 x n32 tile of A[64,128] @ W[128,128] ----------------
__device__ __forceinline__ void mma_phase(
    const __half* A, const __half* B,
    int mrow0, int nbase, int lane, float acc[2][4][4]) {
#pragma unroll
    for (int mi = 0; mi < 2; mi++)
#pragma unroll
        for (int nj = 0; nj < 4; nj++)
#pragma unroll
            for (int c = 0; c < 4; c++) acc[mi][nj][c] = 0.f;

    int arow = mrow0 + (lane & 15);
    int acol = (lane >> 4) << 3;
    int brow = (lane & 15) * WS;
    int bn   = (lane >> 4) << 3;

#pragma unroll
    for (int kt = 0; kt < 8; kt++) {
        uint32_t a[2][4];
#pragma unroll
        for (int mi = 0; mi < 2; mi++)
            ldsm4(sptr(A + (arow + mi * 16) * WS + kt * 16 + acol),
                  a[mi][0], a[mi][1], a[mi][2], a[mi][3]);
#pragma unroll
        for (int ni = 0; ni < 2; ni++) {
            uint32_t b0, b1, b2, b3;
            ldsm4t(sptr(B + kt * 16 * WS + brow + nbase + ni * 16 + bn), b0, b1, b2, b3);
#pragma unroll
            for (int mi = 0; mi < 2; mi++) {
                mma16816(acc[mi][2 * ni],     a[mi][0], a[mi][1], a[mi][2], a[mi][3], b0, b1);
                mma16816(acc[mi][2 * ni + 1], a[mi][0], a[mi][1], a[mi][2], a[mi][3], b2, b3);
            }
        }
    }
}

// ---------------- fused GIN layer (persistent grid-stride, fp16, optional fused pool) ----------------
// smem: W1 (PLANE) + W2 (PLANE) + A (TMWS) + T (TMWS) = 52224 elems = 104448 B -> 2 blocks/SM
#define OFF_A (2 * PLANE)
#define OFF_T (2 * PLANE + TMWS)
#define SMEM_ELEMS (2 * PLANE + 2 * TMWS)

extern __shared__ __half sb[];

__global__ __launch_bounds__(256) void k_layer(
    const __half* __restrict__ A, const float* __restrict__ vscal,
    const float* __restrict__ W1v,
    const __half* __restrict__ W1, const float* __restrict__ b1,
    const __half* __restrict__ W2, const float* __restrict__ b2,
    __half* __restrict__ Out,
    const int* __restrict__ comp, float* __restrict__ outPool,
    int nrows, int mode) {

    __shared__ float sv[TM];
    __shared__ float spool[HN];
    int tid  = threadIdx.x;
    int lane = tid & 31;
    int w    = tid >> 5;
    int mrow0 = (w >> 2) * 32;   // 2 m-groups of 32 rows
    int nbase = (w & 3) * 32;    // 4 n-groups of 32 cols

    __half* sW1 = sb;
    __half* sW2 = sb + PLANE;
    __half* sA  = sb + OFF_A;
    __half* sT  = sb + OFF_T;

    const int U4 = PLANE * 2 / 16;
    for (int i = tid; i < U4; i += 256) {
        ((uint4*)sW2)[i] = ((const uint4*)W2)[i];
        if (mode != 0) ((uint4*)sW1)[i] = ((const uint4*)W1)[i];
    }

    int ntiles = (nrows + TM - 1) / TM;
    for (int t = blockIdx.x; t < ntiles; t += gridDim.x) {
        int row0 = t * TM;
        int tr = nrows - row0; if (tr > TM) tr = TM;
        __syncthreads();

        if (mode == 0) {
            if (tid < TM) sv[tid] = (tid < tr) ? vscal[row0 + tid] : 0.f;
            __syncthreads();
            for (int i = tid; i < TM * HN; i += 256) {
                int r = i >> 7, c = i & 127;
                float v = fmaxf(fmaf(sv[r], __ldg(W1v + c), __ldg(b1 + c)), 0.f);
                sT[r * WS + c] = __float2half_rn(v);
            }
            __syncthreads();
        } else {
            if (mode == 2 && tid < HN) spool[tid] = 0.f;
            // load A tile (fp16, 8 elems per uint4)
            for (int i = tid; i < TM * HN / 8; i += 256) {
                int e = i * 8, r = e >> 7, c = e & 127;
                uint4 v = make_uint4(0u, 0u, 0u, 0u);
                if (r < tr) v = __ldg((const uint4*)(A + (size_t)(row0 + r) * HN + c));
                *(uint4*)(sA + r * WS + c) = v;
            }
            __syncthreads();

            float acc[2][4][4];
            mma_phase(sA, sW1, mrow0, nbase, lane, acc);

#pragma unroll
            for (int mi = 0; mi < 2; mi++) {
                int r0 = mrow0 + mi * 16 + (lane >> 2);
#pragma unroll
                for (int nj = 0; nj < 4; nj++) {
                    int c = nbase + nj * 8 + (lane & 3) * 2;
                    float bx = __ldg(b1 + c), by = __ldg(b1 + c + 1);
                    *(__half2*)(sT + r0 * WS + c) =
                        __floats2half2_rn(fmaxf(acc[mi][nj][0] + bx, 0.f),
                                          fmaxf(acc[mi][nj][1] + by, 0.f));
                    *(__half2*)(sT + (r0 + 8) * WS + c) =
                        __floats2half2_rn(fmaxf(acc[mi][nj][2] + bx, 0.f),
                                          fmaxf(acc[mi][nj][3] + by, 0.f));
                }
            }
            __syncthreads();
        }

        // phase 2: relu(T @ W2 + b2)
        float acc[2][4][4];
        mma_phase(sT, sW2, mrow0, nbase, lane, acc);

        if (mode == 2) {
            int gfirst = __ldg(comp + row0);
            int glast  = __ldg(comp + row0 + tr - 1);
            if (gfirst == glast) {
                // fast path: whole tile pools into one graph; warp shfl column-reduce
#pragma unroll
                for (int mi = 0; mi < 2; mi++) {
                    int r0 = mrow0 + mi * 16 + (lane >> 2);
#pragma unroll
                    for (int nj = 0; nj < 4; nj++) {
                        int c = nbase + nj * 8 + (lane & 3) * 2;
                        float bx = __ldg(b2 + c), by = __ldg(b2 + c + 1);
                        float v0 = 0.f, v1 = 0.f;
                        if (r0 < tr)     { v0 += fmaxf(acc[mi][nj][0] + bx, 0.f);
                                           v1 += fmaxf(acc[mi][nj][1] + by, 0.f); }
                        if (r0 + 8 < tr) { v0 += fmaxf(acc[mi][nj][2] + bx, 0.f);
                                           v1 += fmaxf(acc[mi][nj][3] + by, 0.f); }
#pragma unroll
                        for (int o = 4; o <= 16; o <<= 1) {
                            v0 += __shfl_xor_sync(0xffffffffu, v0, o);
                            v1 += __shfl_xor_sync(0xffffffffu, v1, o);
                        }
                        if (lane < 4) {
                            atomicAdd(&spool[c], v0);
                            atomicAdd(&spool[c + 1], v1);
                        }
                    }
                }
                __syncthreads();
                if (tid < HN) atomicAdd(outPool + (size_t)gfirst * HN + tid, spool[tid]);
            } else {
                // boundary tile (rare): per-element global atomics
#pragma unroll
                for (int mi = 0; mi < 2; mi++) {
                    int r0 = mrow0 + mi * 16 + (lane >> 2);
#pragma unroll
                    for (int nj = 0; nj < 4; nj++) {
                        int c = nbase + nj * 8 + (lane & 3) * 2;
                        float bx = __ldg(b2 + c), by = __ldg(b2 + c + 1);
                        if (r0 < tr) {
                            int g = __ldg(comp + row0 + r0);
                            atomicAdd(outPool + (size_t)g * HN + c,
                                      fmaxf(acc[mi][nj][0] + bx, 0.f));
                            atomicAdd(outPool + (size_t)g * HN + c + 1,
                                      fmaxf(acc[mi][nj][1] + by, 0.f));
                        }
                        if (r0 + 8 < tr) {
                            int g = __ldg(comp + row0 + r0 + 8);
                            atomicAdd(outPool + (size_t)g * HN + c,
                                      fmaxf(acc[mi][nj][2] + bx, 0.f));
                            atomicAdd(outPool + (size_t)g * HN + c + 1,
                                      fmaxf(acc[mi][nj][3] + by, 0.f));
                        }
                    }
                }
            }
        } else {
#pragma unroll
            for (int mi = 0; mi < 2; mi++) {
                int r0 = mrow0 + mi * 16 + (lane >> 2);
#pragma unroll
                for (int nj = 0; nj < 4; nj++) {
                    int c = nbase + nj * 8 + (lane & 3) * 2;
                    float bx = __ldg(b2 + c), by = __ldg(b2 + c + 1);
                    int gr0 = row0 + r0, gr1 = gr0 + 8;
                    if (gr0 < nrows)
                        *(__half2*)(Out + (size_t)gr0 * HN + c) =
                            __floats2half2_rn(fmaxf(acc[mi][nj][0] + bx, 0.f),
                                              fmaxf(acc[mi][nj][1] + by, 0.f));
                    if (gr1 < nrows)
                        *(__half2*)(Out + (size_t)gr1 * HN + c) =
                            __floats2half2_rn(fmaxf(acc[mi][nj][2] + bx, 0.f),
                                              fmaxf(acc[mi][nj][3] + by, 0.f));
                }
            }
        }
    }
}

// ---------------- launch ----------------
extern "C" void kernel_launch(void* const* d_in, const int* in_sizes, int n_in,
                              void* d_out, int out_size) {
    const float* x     = (const float*)d_in[0];
    const void*  ei    = d_in[1];
    const void*  n2s   = d_in[2];
    const void*  s2g_i = d_in[3];
    const float* c1W1  = (const float*)d_in[4];
    const float* c1b1  = (const float*)d_in[5];
    const float* c1W2  = (const float*)d_in[6];
    const float* c1b2  = (const float*)d_in[7];
    const float* cW1   = (const float*)d_in[8];
    const float* cb1   = (const float*)d_in[9];
    const float* cW2   = (const float*)d_in[10];
    const float* cb2   = (const float*)d_in[11];

    int N = in_sizes[0];
    int E = in_sizes[1] / 2;
    int G = out_size / HN;

    __half *hA, *hB, *wh;
    float *agg0;
    int *eiX, *comp, *deg, *offs, *cursor, *csr, *bsum, *boffs;
    cudaGetSymbolAddress((void**)&hA,     g_hA);
    cudaGetSymbolAddress((void**)&hB,     g_hB);
    cudaGetSymbolAddress((void**)&agg0,   g_agg0);
    cudaGetSymbolAddress((void**)&eiX,    g_ei);
    cudaGetSymbolAddress((void**)&comp,   g_comp);
    cudaGetSymbolAddress((void**)&deg,    g_deg);
    cudaGetSymbolAddress((void**)&offs,   g_offs);
    cudaGetSymbolAddress((void**)&cursor, g_cursor);
    cudaGetSymbolAddress((void**)&csr,    g_csr);
    cudaGetSymbolAddress((void**)&bsum,   g_bsum);
    cudaGetSymbolAddress((void**)&boffs,  g_boffs);
    cudaGetSymbolAddress((void**)&wh,     g_whalf);

    const int SMEM = SMEM_ELEMS * 2;   // 104448 B -> 2 blocks/SM
    cudaFuncSetAttribute(k_layer, cudaFuncAttributeMaxDynamicSharedMemorySize, SMEM);

    // init (parallel detect), merged setup (zero + comp + W convert), index convert
    k_init<<<1, 64>>>((const unsigned long long*)ei);
    int setup_items = N + 5 * HN * HN;
    k_setup<<<(setup_items + 255) / 256, 256>>>(n2s, s2g_i, comp, deg, cursor,
                                                c1W2, cW1, cW2, wh, N);
    k_convert_ei<<<(2 * E + 255) / 256, 256>>>(ei, eiX, deg, E);

    // CSR build (dst-major): 3-pass multi-block scan + scatter
    int nscan = (N + SCHUNK - 1) / SCHUNK;     // 98 for N=100000
    k_scan1<<<nscan, 256>>>(deg, bsum, N);
    k_scan2<<<1, 128>>>(bsum, boffs, offs, nscan, N);
    k_scan3<<<nscan, 256>>>(deg, boffs, offs, N);
    k_scatter<<<(E + 255) / 256, 256>>>(eiX, eiX + E, offs, cursor, csr, E);

    int ablocks0 = (N * 32 + 255) / 256;       // warp-per-node (k_agg0)
    int ablocks  = (N * 16 + 255) / 256;       // half-warp-per-node (k_agg_csr)
    const int LGRID = 296;   // 2 blocks/SM

    // layer 1: scalar agg + fused expansion/MMA -> hB
    k_agg0<<<ablocks0, 256>>>(offs, csr, x, agg0, N);
    k_layer<<<LGRID, 256, SMEM>>>(nullptr, agg0, c1W1, nullptr, c1b1,
                                  wh + 0 * PLANE, c1b2, hB,
                                  nullptr, nullptr, N, 0);

    // layer 2: agg + dual MMA -> hB
    k_agg_csr<<<ablocks, 256>>>(offs, csr, hB, hA, N);
    k_layer<<<LGRID, 256, SMEM>>>(hA, nullptr, nullptr,
                                  wh + 1 * PLANE, cb1, wh + 2 * PLANE, cb2, hB,
                                  nullptr, nullptr, N, 1);

    // layer 3: agg + dual MMA with fused pooling -> d_out
    k_agg_csr<<<ablocks, 256>>>(offs, csr, hB, hA, N);
    k_zero4<<<((G * HN / 4) + 255) / 256, 256>>>((float*)d_out, G * HN / 4);
    k_layer<<<LGRID, 256, SMEM>>>(hA, nullptr, nullptr,
                                  wh + 3 * PLANE, cb1 + HN, wh + 4 * PLANE, cb2 + HN,
                                  nullptr, comp, (float*)d_out, N, 2);
}